// round 1
// baseline (speedup 1.0000x reference)
#include <cuda_runtime.h>
#include <math.h>

#define BS_TOK 12736   // 64*199
#define BB 64
#define SS 199

// ---------------- scratch (device globals; no allocation allowed) ----------
__device__ float g_h   [BS_TOK*256];
__device__ float g_xn  [BS_TOK*256];
__device__ float g_big [BS_TOK*1024];   // xi / Wx / ffn-mid
__device__ float g_xca [BS_TOK*512];
__device__ float g_q   [BS_TOK*512];    // also attention output (in-place)
__device__ float g_k   [BS_TOK*512];
__device__ float g_v   [BS_TOK*512];
__device__ float g_hs  [BS_TOK*512];    // h_state / slstm y / ffn act
__device__ float g_ig  [BB*4*SS];
__device__ float g_fg  [BB*4*SS];
__device__ float g_a   [BB*4*SS];
__device__ float g_m   [BB*4*SS];
__device__ float g_e   [BB*4*SS];
__device__ float g_pool[BB*256];

// ---------------- helpers ---------------------------------------------------
__device__ __forceinline__ float warp_sum(float v) {
#pragma unroll
    for (int o = 16; o; o >>= 1) v += __shfl_xor_sync(0xffffffffu, v, o);
    return v;
}
__device__ __forceinline__ float log_sigmoid(float x) {
    return (x >= 0.f) ? -log1pf(expf(-x)) : x - log1pf(expf(x));
}
__device__ __forceinline__ float sigmoidf_(float x) {
    return 1.f / (1.f + expf(-x));
}

// ---------------- GEMM: C[M,N] (+bias) (+=) = A[M,K] @ B[K,N] ---------------
// BM=64, BN=128, BK=16; 256 threads; 4x8 microtile. Requires M%64==0, N%128==0, K%16==0.
__global__ void gemm_kernel(const float* __restrict__ A, const float* __restrict__ B,
                            float* __restrict__ C, int M, int N, int K,
                            const float* __restrict__ bias, int addC)
{
    __shared__ float As[16][64];
    __shared__ float Bs[16][128];
    int tid  = threadIdx.x;
    int brow = blockIdx.y * 64;
    int bcol = blockIdx.x * 128;
    int tr = (tid >> 4) << 2;     // 0..60
    int tc = (tid & 15) << 3;     // 0..120
    float acc[4][8];
#pragma unroll
    for (int i = 0; i < 4; i++)
#pragma unroll
        for (int j = 0; j < 8; j++) acc[i][j] = 0.f;

    int la_r = tid >> 2, la_c = (tid & 3) << 2;
    int lb_r = tid >> 4, lb_c = (tid & 15) << 3;

    for (int k0 = 0; k0 < K; k0 += 16) {
        float4 av = *(const float4*)(A + (size_t)(brow + la_r) * K + k0 + la_c);
        As[la_c + 0][la_r] = av.x; As[la_c + 1][la_r] = av.y;
        As[la_c + 2][la_r] = av.z; As[la_c + 3][la_r] = av.w;
        const float* bp = B + (size_t)(k0 + lb_r) * N + bcol + lb_c;
        *(float4*)&Bs[lb_r][lb_c]     = *(const float4*)bp;
        *(float4*)&Bs[lb_r][lb_c + 4] = *(const float4*)(bp + 4);
        __syncthreads();
#pragma unroll
        for (int kk = 0; kk < 16; kk++) {
            float4 a4  = *(const float4*)(&As[kk][tr]);
            float4 b4l = *(const float4*)(&Bs[kk][tc]);
            float4 b4h = *(const float4*)(&Bs[kk][tc + 4]);
            float ar[4] = {a4.x, a4.y, a4.z, a4.w};
            float br[8] = {b4l.x, b4l.y, b4l.z, b4l.w, b4h.x, b4h.y, b4h.z, b4h.w};
#pragma unroll
            for (int i = 0; i < 4; i++)
#pragma unroll
                for (int j = 0; j < 8; j++)
                    acc[i][j] = fmaf(ar[i], br[j], acc[i][j]);
        }
        __syncthreads();
    }
#pragma unroll
    for (int i = 0; i < 4; i++) {
        float* cp = C + (size_t)(brow + tr + i) * N + bcol + tc;
#pragma unroll
        for (int jh = 0; jh < 2; jh++) {
            float4 r;
            r.x = acc[i][jh * 4 + 0]; r.y = acc[i][jh * 4 + 1];
            r.z = acc[i][jh * 4 + 2]; r.w = acc[i][jh * 4 + 3];
            if (bias) {
                const float* bb = bias + bcol + tc + jh * 4;
                r.x += bb[0]; r.y += bb[1]; r.z += bb[2]; r.w += bb[3];
            }
            if (addC) {
                float4 c0 = *(const float4*)(cp + jh * 4);
                r.x += c0.x; r.y += c0.y; r.z += c0.z; r.w += c0.w;
            }
            *(float4*)(cp + jh * 4) = r;
        }
    }
}

// ---------------- LayerNorm over 256 (optional SELU) ------------------------
__global__ void ln_kernel(const float* __restrict__ x, const float* __restrict__ w,
                          float* __restrict__ out, int rows, int do_selu)
{
    int warp = threadIdx.x >> 5, lane = threadIdx.x & 31;
    int row = blockIdx.x * 8 + warp;
    if (row >= rows) return;
    const float* xr = x + (size_t)row * 256;
    float v[8], s = 0.f, sq = 0.f;
#pragma unroll
    for (int i = 0; i < 8; i++) { v[i] = xr[lane + 32 * i]; s += v[i]; sq += v[i] * v[i]; }
    s = warp_sum(s); sq = warp_sum(sq);
    float mu  = s * (1.f / 256.f);
    float var = sq * (1.f / 256.f) - mu * mu;
    float inv = rsqrtf(var + 1e-5f);
    float* orow = out + (size_t)row * 256;
#pragma unroll
    for (int i = 0; i < 8; i++) {
        float y = (v[i] - mu) * inv * w[lane + 32 * i];
        if (do_selu)
            y = (y > 0.f) ? 1.0507009873554805f * y
                          : 1.0507009873554805f * 1.6732632423543772f * (expf(y) - 1.f);
        orow[lane + 32 * i] = y;
    }
}

// ---------------- causal depthwise conv (K=4) + SiLU ------------------------
__global__ void conv_silu_kernel(const float* __restrict__ x, const float* __restrict__ w,
                                 const float* __restrict__ bias, float* __restrict__ out,
                                 int C, int in_stride)
{
    int idx = blockIdx.x * blockDim.x + threadIdx.x;
    if (idx >= BS_TOK * C) return;
    int c   = idx % C;
    int tok = idx / C;
    int t = tok % SS, b = tok / SS;
    float acc = bias[c];
    const float* xb = x + (size_t)(b * SS) * in_stride + c;
#pragma unroll
    for (int i = 0; i < 4; i++) {
        int tt = t - 3 + i;
        if (tt >= 0) acc += xb[(size_t)tt * in_stride] * w[c * 4 + i];
    }
    out[(size_t)tok * C + c] = acc * sigmoidf_(acc);
}

// ---------------- headwise 4x4 projection (128 heads of 4) ------------------
__global__ void headwise_kernel(const float* __restrict__ x, int in_stride,
                                const float* __restrict__ w, float* __restrict__ out)
{
    int idx = blockIdx.x * blockDim.x + threadIdx.x;   // BS_TOK*128
    if (idx >= BS_TOK * 128) return;
    int h = idx & 127, tok = idx >> 7;
    const float4 xv = *(const float4*)(x + (size_t)tok * in_stride + h * 4);
    const float* wp = w + h * 16;
    float4 o;
    o.x = xv.x * wp[0]  + xv.y * wp[1]  + xv.z * wp[2]  + xv.w * wp[3];
    o.y = xv.x * wp[4]  + xv.y * wp[5]  + xv.z * wp[6]  + xv.w * wp[7];
    o.z = xv.x * wp[8]  + xv.y * wp[9]  + xv.z * wp[10] + xv.w * wp[11];
    o.w = xv.x * wp[12] + xv.y * wp[13] + xv.z * wp[14] + xv.w * wp[15];
    *(float4*)(out + (size_t)tok * 512 + h * 4) = o;
}

// ---------------- mLSTM i/f gates: dot(concat(q,k,v), W[n]) + b --------------
__global__ void mgates_kernel(const float* __restrict__ q, const float* __restrict__ k,
                              const float* __restrict__ v,
                              const float* __restrict__ igw, const float* __restrict__ igb,
                              const float* __restrict__ fgw, const float* __restrict__ fgb,
                              float* __restrict__ ig, float* __restrict__ fg)
{
    int wid  = (blockIdx.x * blockDim.x + threadIdx.x) >> 5;
    int lane = threadIdx.x & 31;
    int tok = wid >> 3, r = wid & 7;
    int n = r >> 1, isf = r & 1;
    const float* wrow = (isf ? fgw : igw) + n * 1536;
    size_t o5 = (size_t)tok * 512;
    float s = 0.f;
    for (int j = lane; j < 512; j += 32)
        s += q[o5 + j] * wrow[j] + k[o5 + j] * wrow[512 + j] + v[o5 + j] * wrow[1024 + j];
    s = warp_sum(s);
    if (lane == 0) {
        int b = tok / SS, ss = tok % SS;
        float val = s + (isf ? fgb[n] : igb[n]);
        (isf ? fg : ig)[(b * 4 + n) * SS + ss] = val;
    }
}

// ---------------- per-(b,n) sequential gate prep (cumsum / prefix-max) ------
__global__ void gateprep_kernel(const float* __restrict__ ig, const float* __restrict__ fg,
                                float* __restrict__ a, float* __restrict__ m,
                                float* __restrict__ e)
{
    if (threadIdx.x != 0) return;
    int bn = blockIdx.x;
    const float* igp = ig + bn * SS;
    const float* fgp = fg + bn * SS;
    float lfc = 0.f, rm = -INFINITY;
    for (int t = 0; t < SS; t++) {
        lfc += log_sigmoid(fgp[t]);          // lfc[t+1]
        float at = igp[t] - lfc;
        rm = fmaxf(rm, at);
        a[bn * SS + t] = at;
        m[bn * SS + t] = rm;
        e[bn * SS + t] = expf(-(rm + lfc));  // exp(-maxD[t])
    }
}

// ---------------- mLSTM parallel attention (one CTA per (b,n,s)) ------------
#define ATTN_SMEM ((SS*129 + 128 + 200 + 8) * 4)
__global__ void attn_kernel(const float* __restrict__ q, const float* __restrict__ k,
                            const float* __restrict__ v,
                            const float* __restrict__ a, const float* __restrict__ m,
                            const float* __restrict__ e, float* __restrict__ out)
{
    extern __shared__ float sm[];
    float* ksm = sm;                 // SS*129
    float* qsm = ksm + SS * 129;     // 128
    float* wsm = qsm + 128;          // 200
    float* red = wsm + 200;          // 8
    int bn = blockIdx.x, s = blockIdx.y;
    int b = bn >> 2, n = bn & 3;
    int tid = threadIdx.x;

    const float* qrow = q + ((size_t)(b * SS + s)) * 512 + n * 128;
    if (tid < 128) qsm[tid] = qrow[tid];
    int nelem = (s + 1) * 128;
    const float* kbase = k + ((size_t)(b * SS)) * 512 + n * 128;
    for (int i = tid; i < nelem; i += 256) {
        int t = i >> 7, d = i & 127;
        ksm[t * 129 + d] = kbase[(size_t)t * 512 + d];
    }
    __syncthreads();

    const float* abn = a + bn * SS;
    float ms = m[bn * SS + s], es = e[bn * SS + s];
    const float scale = 0.08838834764831845f;  // 1/sqrt(128)
    float lsum = 0.f;
    for (int t = tid; t <= s; t += 256) {
        float dot = 0.f;
        const float* kr = &ksm[t * 129];
#pragma unroll 8
        for (int d = 0; d < 128; d++) dot = fmaf(qsm[d], kr[d], dot);
        float w = dot * scale * expf(abn[t] - ms);
        wsm[t] = w;
        lsum += w;
    }
    lsum = warp_sum(lsum);
    if ((tid & 31) == 0) red[tid >> 5] = lsum;
    __syncthreads();
    float total = red[0] + red[1] + red[2] + red[3] + red[4] + red[5] + red[6] + red[7];
    float norm = fmaxf(fabsf(total), es) + 1e-6f;

    if (tid < 128) {
        float accv = 0.f;
        const float* vbase = v + ((size_t)(b * SS)) * 512 + n * 128 + tid;
        for (int t = 0; t <= s; t++) accv = fmaf(wsm[t], vbase[(size_t)t * 512], accv);
        out[((size_t)(b * SS + s)) * 512 + n * 128 + tid] = accv / norm;
    }
}

// ---------------- per-head LN(128) + skip + z-gate ---------------------------
__global__ void hstate_kernel(const float* __restrict__ attn, const float* __restrict__ xca,
                              const float* __restrict__ xi, const float* __restrict__ onw,
                              const float* __restrict__ skip, float* __restrict__ out)
{
    __shared__ float red[8];
    int tok = blockIdx.x, n = blockIdx.y, c = threadIdx.x;  // 128 threads
    size_t i512 = (size_t)tok * 512 + n * 128 + c;
    float v = attn[i512];
    float s = warp_sum(v), sq = warp_sum(v * v);
    if ((c & 31) == 0) { red[c >> 5] = s; red[4 + (c >> 5)] = sq; }
    __syncthreads();
    float ts = red[0] + red[1] + red[2] + red[3];
    float tq = red[4] + red[5] + red[6] + red[7];
    float mu = ts * (1.f / 128.f);
    float var = tq * (1.f / 128.f) - mu * mu;
    float inv = rsqrtf(var + 1e-5f);
    int wc = n * 128 + c;
    float hn = (v - mu) * inv * onw[wc];
    float z = xi[(size_t)tok * 1024 + 512 + wc];
    out[i512] = (hn + skip[wc] * xca[i512]) * (z * sigmoidf_(z));
}

// ---------------- sLSTM Wx gates (16 tiny GEMMs) -----------------------------
__global__ void slstm_wx_kernel(const float* __restrict__ xc, const float* __restrict__ xn,
                                const float* __restrict__ gate_w, float* __restrict__ wx)
{
    __shared__ float wsm[64 * 65];
    __shared__ float xsm[32 * 64];
    int gh = blockIdx.x;            // g*4+h
    int g = gh >> 2, h = gh & 3;
    const float* in = (g < 2) ? xc : xn;
    const float* wg = gate_w + (size_t)gh * 4096;   // [o][d]
    int tid = threadIdx.x;
    for (int i = tid; i < 4096; i += 256) { int o = i >> 6, d = i & 63; wsm[o * 65 + d] = wg[i]; }
    int tok0 = blockIdx.y * 32;
    for (int i = tid; i < 2048; i += 256) {
        int tl = i >> 6, d = i & 63;
        xsm[i] = in[(size_t)(tok0 + tl) * 256 + h * 64 + d];
    }
    __syncthreads();
    int tl = tid >> 3;
    int obase = (tid & 7) << 3;
    const float* xr = &xsm[tl * 64];
    float acc[8] = {0, 0, 0, 0, 0, 0, 0, 0};
    for (int d = 0; d < 64; d++) {
        float xv = xr[d];
#pragma unroll
        for (int j = 0; j < 8; j++) acc[j] = fmaf(xv, wsm[(obase + j) * 65 + d], acc[j]);
    }
    size_t base = (size_t)(tok0 + tl) * 1024 + gh * 64 + obase;
#pragma unroll
    for (int j = 0; j < 8; j++) wx[base + j] = acc[j];
}

// ---------------- sLSTM recurrent scan (one CTA per (b,head)) ----------------
#define SCAN_SMEM ((4*64*65 + 64 + 256) * 4)
__global__ void slstm_scan_kernel(const float* __restrict__ wx, const float* __restrict__ recw,
                                  const float* __restrict__ bias, float* __restrict__ y)
{
    extern __shared__ float sm[];
    float* rec  = sm;                 // 4*64*65
    float* hsm  = rec + 4 * 64 * 65;  // 64
    float* raws = hsm + 64;           // 256
    int bh = blockIdx.x;
    int b = bh >> 2, h = bh & 3;
    int tid = threadIdx.x;
    int g = tid >> 6, o = tid & 63;
    for (int i = tid; i < 4 * 64 * 64; i += 256) {
        int gg = i >> 12, oo = (i >> 6) & 63, dd = i & 63;
        rec[(gg * 64 + oo) * 65 + dd] = recw[(size_t)((gg * 4 + h) * 64 + oo) * 64 + dd];
    }
    float bval = bias[(g * 4 + h) * 64 + o];
    if (tid < 64) hsm[tid] = 0.f;
    float c = 0.f, nn = 0.f, mm = 0.f;
    __syncthreads();
    const float* rrow = &rec[(g * 64 + o) * 65];
    for (int s = 0; s < SS; s++) {
        float raw = wx[((size_t)(b * SS + s)) * 1024 + (g * 4 + h) * 64 + o] + bval;
#pragma unroll 8
        for (int d = 0; d < 64; d++) raw = fmaf(hsm[d], rrow[d], raw);
        raws[tid] = raw;
        __syncthreads();
        if (tid < 64) {
            float i_ = raws[o], f_ = raws[64 + o], z_ = raws[128 + o], o_ = raws[192 + o];
            float lfm = mm + log_sigmoid(f_);
            float mn = fmaxf(i_, lfm);
            float ign = expf(i_ - mn), fgn = expf(lfm - mn);
            c  = fgn * c  + ign * tanhf(z_);
            nn = fgn * nn + ign;
            mm = mn;
            float hv = sigmoidf_(o_) * (c / nn);
            hsm[o] = hv;
            y[((size_t)(b * SS + s)) * 256 + h * 64 + o] = hv;
        }
        __syncthreads();
    }
}

// ---------------- sLSTM group norm (per-head LN over 64) + residual ----------
__global__ void slstm_gn_kernel(const float* __restrict__ y, const float* __restrict__ w,
                                float* __restrict__ h_io)
{
    int tok = blockIdx.x;
    int h = threadIdx.x >> 5, lane = threadIdx.x & 31;
    size_t base = (size_t)tok * 256 + h * 64;
    float v0 = y[base + lane], v1 = y[base + 32 + lane];
    float s = warp_sum(v0 + v1);
    float sq = warp_sum(v0 * v0 + v1 * v1);
    float mu = s * (1.f / 64.f);
    float var = sq * (1.f / 64.f) - mu * mu;
    float inv = rsqrtf(var + 1e-5f);
    h_io[base + lane]      += (v0 - mu) * inv * w[h * 64 + lane];
    h_io[base + 32 + lane] += (v1 - mu) * inv * w[h * 64 + 32 + lane];
}

// ---------------- gated FFN activation ---------------------------------------
__global__ void gelu_gate_kernel(const float* __restrict__ mid, float* __restrict__ act)
{
    int idx = blockIdx.x * blockDim.x + threadIdx.x;
    if (idx >= BS_TOK * 384) return;
    int tok = idx / 384, j = idx % 384;
    float gt = mid[(size_t)tok * 768 + j];
    float up = mid[(size_t)tok * 768 + 384 + j];
    float t = tanhf(0.7978845608028654f * (gt + 0.044715f * gt * gt * gt));
    act[(size_t)tok * 384 + j] = 0.5f * gt * (1.f + t) * up;
}

// ---------------- mean pool over S -------------------------------------------
__global__ void pool_kernel(const float* __restrict__ xn, float* __restrict__ pooled)
{
    int b = blockIdx.x, c = threadIdx.x;
    float acc = 0.f;
    for (int s = 0; s < SS; s++) acc += xn[((size_t)(b * SS + s)) * 256 + c];
    pooled[b * 256 + c] = acc * (1.f / 199.f);
}

// ---------------- classification heads ---------------------------------------
__global__ void heads_kernel(const float* __restrict__ pooled,
                             const float* __restrict__ we, const float* __restrict__ be,
                             const float* __restrict__ ws, const float* __restrict__ bs_,
                             float* __restrict__ out)
{
    __shared__ float p[256];
    int b = blockIdx.x, tid = threadIdx.x;
    p[tid] = pooled[b * 256 + tid];
    __syncthreads();
    if (tid < 7) {
        float a = be[tid];
        for (int i = 0; i < 256; i++) a = fmaf(p[i], we[i * 7 + tid], a);
        out[b * 7 + tid] = a;
    } else if (tid < 10) {
        int j = tid - 7;
        float a = bs_[j];
        for (int i = 0; i < 256; i++) a = fmaf(p[i], ws[i * 3 + j], a);
        out[BB * 7 + b * 3 + j] = a;
    }
}

// ---------------- host orchestration -----------------------------------------
extern "C" void kernel_launch(void* const* d_in, const int* in_sizes, int n_in,
                              void* d_out, int out_size)
{
    (void)in_sizes; (void)n_in; (void)out_size;
    const float* x          = (const float*)d_in[0];
    const float* w_down     = (const float*)d_in[1];
    const float* b_down     = (const float*)d_in[2];
    const float* m_ln_w     = (const float*)d_in[3];
    const float* m_proj_up  = (const float*)d_in[4];
    const float* m_conv_w   = (const float*)d_in[5];
    const float* m_conv_b   = (const float*)d_in[6];
    const float* m_q_w      = (const float*)d_in[7];
    const float* m_k_w      = (const float*)d_in[8];
    const float* m_v_w      = (const float*)d_in[9];
    const float* m_ig_w     = (const float*)d_in[10];
    const float* m_ig_b     = (const float*)d_in[11];
    const float* m_fg_w     = (const float*)d_in[12];
    const float* m_fg_b     = (const float*)d_in[13];
    const float* m_skip     = (const float*)d_in[14];
    const float* m_outnorm  = (const float*)d_in[15];
    const float* m_proj_dn  = (const float*)d_in[16];
    const float* s_ln_w     = (const float*)d_in[17];
    const float* s_conv_w   = (const float*)d_in[18];
    const float* s_conv_b   = (const float*)d_in[19];
    const float* s_gate_w   = (const float*)d_in[20];
    const float* s_rec_w    = (const float*)d_in[21];
    const float* s_bias     = (const float*)d_in[22];
    const float* s_gn_w     = (const float*)d_in[23];
    const float* s_ln2_w    = (const float*)d_in[24];
    const float* s_ffn_up   = (const float*)d_in[25];
    const float* s_ffn_dn   = (const float*)d_in[26];
    const float* post_ln_w  = (const float*)d_in[27];
    const float* w_emo      = (const float*)d_in[28];
    const float* b_emo      = (const float*)d_in[29];
    const float* w_sen      = (const float*)d_in[30];
    const float* b_sen      = (const float*)d_in[31];

    float *h_, *xn_, *big_, *xca_, *q_, *k_, *v_, *hs_;
    float *ig_, *fg_, *a_, *mm_, *e_, *pool_;
    cudaGetSymbolAddress((void**)&h_,   g_h);
    cudaGetSymbolAddress((void**)&xn_,  g_xn);
    cudaGetSymbolAddress((void**)&big_, g_big);
    cudaGetSymbolAddress((void**)&xca_, g_xca);
    cudaGetSymbolAddress((void**)&q_,   g_q);
    cudaGetSymbolAddress((void**)&k_,   g_k);
    cudaGetSymbolAddress((void**)&v_,   g_v);
    cudaGetSymbolAddress((void**)&hs_,  g_hs);
    cudaGetSymbolAddress((void**)&ig_,  g_ig);
    cudaGetSymbolAddress((void**)&fg_,  g_fg);
    cudaGetSymbolAddress((void**)&a_,   g_a);
    cudaGetSymbolAddress((void**)&mm_,  g_m);
    cudaGetSymbolAddress((void**)&e_,   g_e);
    cudaGetSymbolAddress((void**)&pool_, g_pool);

    cudaFuncSetAttribute(attn_kernel, cudaFuncAttributeMaxDynamicSharedMemorySize, ATTN_SMEM);
    cudaFuncSetAttribute(slstm_scan_kernel, cudaFuncAttributeMaxDynamicSharedMemorySize, SCAN_SMEM);

    const int LN_GRID = BS_TOK / 8;  // 1592

    // h = x @ w_down + b_down
    gemm_kernel<<<dim3(2, 199), 256>>>(x, w_down, h_, BS_TOK, 256, 1024, b_down, 0);

    int mi = 0, si = 0;
    for (int blk = 0; blk < 7; blk++) {
        if (blk == 1 || blk == 4) {
            // ---- sLSTM block ----
            ln_kernel<<<LN_GRID, 256>>>(h_, s_ln_w + si * 256, xn_, BS_TOK, 0);
            conv_silu_kernel<<<(BS_TOK * 256 + 255) / 256, 256>>>(
                xn_, s_conv_w + si * 1024, s_conv_b + si * 256, xca_, 256, 256);
            slstm_wx_kernel<<<dim3(16, BS_TOK / 32), 256>>>(
                xca_, xn_, s_gate_w + (size_t)si * 65536, big_);
            slstm_scan_kernel<<<256, 256, SCAN_SMEM>>>(
                big_, s_rec_w + (size_t)si * 65536, s_bias + si * 1024, hs_);
            slstm_gn_kernel<<<BS_TOK, 128>>>(hs_, s_gn_w + si * 256, h_);
            // FFN
            ln_kernel<<<LN_GRID, 256>>>(h_, s_ln2_w + si * 256, xn_, BS_TOK, 0);
            gemm_kernel<<<dim3(6, 199), 256>>>(xn_, s_ffn_up + (size_t)si * 196608, big_,
                                               BS_TOK, 768, 256, nullptr, 0);
            gelu_gate_kernel<<<(BS_TOK * 384 + 255) / 256, 256>>>(big_, hs_);
            gemm_kernel<<<dim3(2, 199), 256>>>(hs_, s_ffn_dn + (size_t)si * 98304, h_,
                                               BS_TOK, 256, 384, nullptr, 1);
            si++;
        } else {
            // ---- mLSTM block ----
            ln_kernel<<<LN_GRID, 256>>>(h_, m_ln_w + mi * 256, xn_, BS_TOK, 0);
            gemm_kernel<<<dim3(8, 199), 256>>>(xn_, m_proj_up + (size_t)mi * 262144, big_,
                                               BS_TOK, 1024, 256, nullptr, 0);
            conv_silu_kernel<<<(BS_TOK * 512 + 255) / 256, 256>>>(
                big_, m_conv_w + mi * 2048, m_conv_b + mi * 512, xca_, 512, 1024);
            headwise_kernel<<<BS_TOK * 128 / 256, 256>>>(xca_, 512, m_q_w + mi * 2048, q_);
            headwise_kernel<<<BS_TOK * 128 / 256, 256>>>(xca_, 512, m_k_w + mi * 2048, k_);
            headwise_kernel<<<BS_TOK * 128 / 256, 256>>>(big_, 1024, m_v_w + mi * 2048, v_);
            mgates_kernel<<<BS_TOK, 256>>>(q_, k_, v_,
                m_ig_w + mi * 6144, m_ig_b + mi * 4,
                m_fg_w + mi * 6144, m_fg_b + mi * 4, ig_, fg_);
            gateprep_kernel<<<256, 32>>>(ig_, fg_, a_, mm_, e_);
            attn_kernel<<<dim3(256, 199), 256, ATTN_SMEM>>>(q_, k_, v_, a_, mm_, e_, q_);
            hstate_kernel<<<dim3(BS_TOK, 4), 128>>>(q_, xca_, big_,
                m_outnorm + mi * 512, m_skip + mi * 512, hs_);
            gemm_kernel<<<dim3(2, 199), 256>>>(hs_, m_proj_dn + (size_t)mi * 131072, h_,
                                               BS_TOK, 256, 512, nullptr, 1);
            mi++;
        }
    }

    // post LN + SELU, mean pool, heads
    ln_kernel<<<LN_GRID, 256>>>(h_, post_ln_w, xn_, BS_TOK, 1);
    pool_kernel<<<BB, 256>>>(xn_, pool_);
    heads_kernel<<<BB, 256>>>(pool_, w_emo, b_emo, w_sen, b_sen, (float*)d_out);
}

// round 2
// speedup vs baseline: 2.1322x; 2.1322x over previous
#include <cuda_runtime.h>
#include <math.h>

#define BS_TOK 12736   // 64*199
#define BB 64
#define SS 199

// ---------------- scratch (device globals; no allocation allowed) ----------
__device__ float g_h   [BS_TOK*256];
__device__ float g_xn  [BS_TOK*256];
__device__ float g_big [BS_TOK*1024];   // xi / Wx / ffn-mid
__device__ float g_xca [BS_TOK*512];
__device__ float g_q   [BS_TOK*512];    // also attention output (in-place)
__device__ float g_k   [BS_TOK*512];
__device__ float g_v   [BS_TOK*512];
__device__ float g_hs  [BS_TOK*512];    // h_state / slstm y / ffn act
__device__ float g_ig  [BB*4*SS];
__device__ float g_fg  [BB*4*SS];
__device__ float g_a   [BB*4*SS];
__device__ float g_m   [BB*4*SS];
__device__ float g_e   [BB*4*SS];
__device__ float g_pool[BB*256];

// ---------------- helpers ---------------------------------------------------
__device__ __forceinline__ float warp_sum(float v) {
#pragma unroll
    for (int o = 16; o; o >>= 1) v += __shfl_xor_sync(0xffffffffu, v, o);
    return v;
}
__device__ __forceinline__ float log_sigmoid(float x) {
    return (x >= 0.f) ? -log1pf(expf(-x)) : x - log1pf(expf(x));
}
__device__ __forceinline__ float sigmoidf_(float x) {
    return 1.f / (1.f + expf(-x));
}

// ---------------- GEMM: C[M,N] (+bias) (+=) = A[M,K] @ B[K,N] ---------------
// BM=128, BN=128, BK=8; 256 threads; 8x8 microtile; double-buffered smem.
// Requires N%128==0, K%8==0. M handled with clamped loads + guarded stores.
__global__ void __launch_bounds__(256, 2)
gemm_kernel(const float* __restrict__ A, const float* __restrict__ B,
            float* __restrict__ C, int M, int N, int K,
            const float* __restrict__ bias, int addC)
{
    __shared__ float As[2][8][132];
    __shared__ float Bs[2][8][128];
    int tid  = threadIdx.x;
    int brow = blockIdx.y * 128;
    int bcol = blockIdx.x * 128;
    int ty = tid >> 4, tx = tid & 15;

    // A loader: one float4 per thread per stage
    int a_r = brow + (tid >> 1);
    if (a_r > M - 1) a_r = M - 1;
    int a_c = (tid & 1) << 2;
    const float* Aptr = A + (size_t)a_r * K + a_c;
    // B loader: one float4 per thread per stage
    int b_kr = tid >> 5;
    int b_c  = (tid & 31) << 2;
    const float* Bptr = B + (size_t)b_kr * N + bcol + b_c;

    float4 av = *(const float4*)Aptr;
    float4 bv = *(const float4*)Bptr;
    As[0][a_c + 0][tid >> 1] = av.x;
    As[0][a_c + 1][tid >> 1] = av.y;
    As[0][a_c + 2][tid >> 1] = av.z;
    As[0][a_c + 3][tid >> 1] = av.w;
    *(float4*)&Bs[0][b_kr][b_c] = bv;
    __syncthreads();

    float acc[8][8];
#pragma unroll
    for (int i = 0; i < 8; i++)
#pragma unroll
        for (int j = 0; j < 8; j++) acc[i][j] = 0.f;

    int nk = K >> 3;
    int buf = 0;
    for (int kt = 0; kt < nk; kt++) {
        bool more = (kt + 1) < nk;
        if (more) {
            av = *(const float4*)(Aptr + (kt + 1) * 8);
            bv = *(const float4*)(Bptr + (size_t)(kt + 1) * 8 * N);
        }
#pragma unroll
        for (int kk = 0; kk < 8; kk++) {
            float4 a0 = *(const float4*)&As[buf][kk][ty * 4];
            float4 a1 = *(const float4*)&As[buf][kk][64 + ty * 4];
            float4 b0 = *(const float4*)&Bs[buf][kk][tx * 4];
            float4 b1 = *(const float4*)&Bs[buf][kk][64 + tx * 4];
            float ar[8] = {a0.x, a0.y, a0.z, a0.w, a1.x, a1.y, a1.z, a1.w};
            float br[8] = {b0.x, b0.y, b0.z, b0.w, b1.x, b1.y, b1.z, b1.w};
#pragma unroll
            for (int i = 0; i < 8; i++)
#pragma unroll
                for (int j = 0; j < 8; j++)
                    acc[i][j] = fmaf(ar[i], br[j], acc[i][j]);
        }
        if (more) {
            As[buf ^ 1][a_c + 0][tid >> 1] = av.x;
            As[buf ^ 1][a_c + 1][tid >> 1] = av.y;
            As[buf ^ 1][a_c + 2][tid >> 1] = av.z;
            As[buf ^ 1][a_c + 3][tid >> 1] = av.w;
            *(float4*)&Bs[buf ^ 1][b_kr][b_c] = bv;
        }
        __syncthreads();
        buf ^= 1;
    }

#pragma unroll
    for (int i = 0; i < 8; i++) {
        int lr = (i < 4) ? (ty * 4 + i) : (64 + ty * 4 + i - 4);
        int r = brow + lr;
        if (r >= M) continue;
#pragma unroll
        for (int jh = 0; jh < 2; jh++) {
            int lc = (jh == 0) ? (tx * 4) : (64 + tx * 4);
            float* cp = C + (size_t)r * N + bcol + lc;
            float4 rv;
            rv.x = acc[i][jh * 4 + 0]; rv.y = acc[i][jh * 4 + 1];
            rv.z = acc[i][jh * 4 + 2]; rv.w = acc[i][jh * 4 + 3];
            if (bias) {
                const float* bb = bias + bcol + lc;
                rv.x += bb[0]; rv.y += bb[1]; rv.z += bb[2]; rv.w += bb[3];
            }
            if (addC) {
                float4 c0 = *(const float4*)cp;
                rv.x += c0.x; rv.y += c0.y; rv.z += c0.z; rv.w += c0.w;
            }
            *(float4*)cp = rv;
        }
    }
}

// ---------------- LayerNorm over 256 (optional SELU) ------------------------
__global__ void ln_kernel(const float* __restrict__ x, const float* __restrict__ w,
                          float* __restrict__ out, int rows, int do_selu)
{
    int warp = threadIdx.x >> 5, lane = threadIdx.x & 31;
    int row = blockIdx.x * 8 + warp;
    if (row >= rows) return;
    const float* xr = x + (size_t)row * 256;
    float v[8], s = 0.f, sq = 0.f;
#pragma unroll
    for (int i = 0; i < 8; i++) { v[i] = xr[lane + 32 * i]; s += v[i]; sq += v[i] * v[i]; }
    s = warp_sum(s); sq = warp_sum(sq);
    float mu  = s * (1.f / 256.f);
    float var = sq * (1.f / 256.f) - mu * mu;
    float inv = rsqrtf(var + 1e-5f);
    float* orow = out + (size_t)row * 256;
#pragma unroll
    for (int i = 0; i < 8; i++) {
        float y = (v[i] - mu) * inv * w[lane + 32 * i];
        if (do_selu)
            y = (y > 0.f) ? 1.0507009873554805f * y
                          : 1.0507009873554805f * 1.6732632423543772f * (expf(y) - 1.f);
        orow[lane + 32 * i] = y;
    }
}

// ---------------- causal depthwise conv (K=4) + SiLU ------------------------
__global__ void conv_silu_kernel(const float* __restrict__ x, const float* __restrict__ w,
                                 const float* __restrict__ bias, float* __restrict__ out,
                                 int C, int in_stride)
{
    int idx = blockIdx.x * blockDim.x + threadIdx.x;
    if (idx >= BS_TOK * C) return;
    int c   = idx % C;
    int tok = idx / C;
    int t = tok % SS, b = tok / SS;
    float acc = bias[c];
    const float* xb = x + (size_t)(b * SS) * in_stride + c;
#pragma unroll
    for (int i = 0; i < 4; i++) {
        int tt = t - 3 + i;
        if (tt >= 0) acc += xb[(size_t)tt * in_stride] * w[c * 4 + i];
    }
    out[(size_t)tok * C + c] = acc * sigmoidf_(acc);
}

// ---------------- headwise 4x4 projection (128 heads of 4) ------------------
__global__ void headwise_kernel(const float* __restrict__ x, int in_stride,
                                const float* __restrict__ w, float* __restrict__ out)
{
    int idx = blockIdx.x * blockDim.x + threadIdx.x;   // BS_TOK*128
    if (idx >= BS_TOK * 128) return;
    int h = idx & 127, tok = idx >> 7;
    const float4 xv = *(const float4*)(x + (size_t)tok * in_stride + h * 4);
    const float* wp = w + h * 16;
    float4 o;
    o.x = xv.x * wp[0]  + xv.y * wp[1]  + xv.z * wp[2]  + xv.w * wp[3];
    o.y = xv.x * wp[4]  + xv.y * wp[5]  + xv.z * wp[6]  + xv.w * wp[7];
    o.z = xv.x * wp[8]  + xv.y * wp[9]  + xv.z * wp[10] + xv.w * wp[11];
    o.w = xv.x * wp[12] + xv.y * wp[13] + xv.z * wp[14] + xv.w * wp[15];
    *(float4*)(out + (size_t)tok * 512 + h * 4) = o;
}

// ---------------- mLSTM i/f gates: weights in smem, one warp per token -------
__global__ void __launch_bounds__(256, 1)
mgates_kernel(const float* __restrict__ q, const float* __restrict__ k,
              const float* __restrict__ v,
              const float* __restrict__ igw, const float* __restrict__ igb,
              const float* __restrict__ fgw, const float* __restrict__ fgb,
              float* __restrict__ ig, float* __restrict__ fg)
{
    __shared__ float wsm[12288];   // igw[4][1536] then fgw[4][1536]
    int tid = threadIdx.x;
    for (int i = tid; i < 6144; i += 256) {
        wsm[i]        = igw[i];
        wsm[6144 + i] = fgw[i];
    }
    __syncthreads();
    int warp = tid >> 5, lane = tid & 31;
    int tok = blockIdx.x * 8 + warp;
    size_t o5 = (size_t)tok * 512;
    float acc[8] = {0.f, 0.f, 0.f, 0.f, 0.f, 0.f, 0.f, 0.f};
    for (int j = lane; j < 512; j += 32) {
        float qv = q[o5 + j], kv = k[o5 + j], vv = v[o5 + j];
#pragma unroll
        for (int r = 0; r < 4; r++) {
            const float* wi = &wsm[r * 1536];
            const float* wf = &wsm[6144 + r * 1536];
            acc[r]     += qv * wi[j] + kv * wi[512 + j] + vv * wi[1024 + j];
            acc[4 + r] += qv * wf[j] + kv * wf[512 + j] + vv * wf[1024 + j];
        }
    }
#pragma unroll
    for (int r = 0; r < 8; r++) acc[r] = warp_sum(acc[r]);
    if (lane == 0) {
        int b = tok / SS, ss2 = tok % SS;
#pragma unroll
        for (int r = 0; r < 4; r++) {
            ig[(b * 4 + r) * SS + ss2] = acc[r] + igb[r];
            fg[(b * 4 + r) * SS + ss2] = acc[4 + r] + fgb[r];
        }
    }
}

// ---------------- per-(b,n) sequential gate prep (cumsum / prefix-max) ------
__global__ void gateprep_kernel(const float* __restrict__ ig, const float* __restrict__ fg,
                                float* __restrict__ a, float* __restrict__ m,
                                float* __restrict__ e)
{
    if (threadIdx.x != 0) return;
    int bn = blockIdx.x;
    const float* igp = ig + bn * SS;
    const float* fgp = fg + bn * SS;
    float lfc = 0.f, rm = -INFINITY;
    for (int t = 0; t < SS; t++) {
        lfc += log_sigmoid(fgp[t]);          // lfc[t+1]
        float at = igp[t] - lfc;
        rm = fmaxf(rm, at);
        a[bn * SS + t] = at;
        m[bn * SS + t] = rm;
        e[bn * SS + t] = expf(-(rm + lfc));  // exp(-maxD[t])
    }
}

// ---------------- flash-style mLSTM attention --------------------------------
// grid (256 bn, 2 s-tiles), 256 threads. Q tile 128 rows resident; K/V tiles of
// 64 streamed. Score: 8x4 microtile on [d][.] transposed smem. Output: 8x8.
#define ATTN2_FLOATS (128*132 + 128*68 + 64*128 + 128*68 + 128*3 + 64)
#define ATTN2_SMEM (ATTN2_FLOATS * 4)
__global__ void __launch_bounds__(256, 1)
attn2_kernel(const float* __restrict__ q, const float* __restrict__ k,
             const float* __restrict__ v,
             const float* __restrict__ a, const float* __restrict__ m,
             const float* __restrict__ e, float* __restrict__ out)
{
    extern __shared__ float sm[];
    float* Qs   = sm;                     // [d][r]  stride 132
    float* Ks   = Qs + 128 * 132;         // [d][c]  stride 68
    float* Vs   = Ks + 128 * 68;          // [t][c]  stride 128
    float* Ws   = Vs + 64 * 128;          // [r][t]  stride 68
    float* rsum = Ws + 128 * 68;          // 128
    float* msm  = rsum + 128;             // 128
    float* esm  = msm + 128;              // 128
    float* asmm = esm + 128;              // 64

    int bn = blockIdx.x, stile = blockIdx.y;
    int b = bn >> 2, n = bn & 3;
    int s0 = stile * 128;
    int tid = threadIdx.x;
    int lane = tid & 31;
    int grp  = tid >> 5;

    const size_t qbase = (size_t)(b * SS) * 512 + n * 128;

    // load Q transposed (rows clamped; invalid rows are masked later)
#pragma unroll 4
    for (int j = 0; j < 16; j++) {
        int r = grp + 8 * j;
        int s = s0 + r;
        int sg = s < SS ? s : SS - 1;
        const float* qrow = q + qbase + (size_t)sg * 512;
#pragma unroll
        for (int kk = 0; kk < 4; kk++) {
            int d = lane + 32 * kk;
            Qs[d * 132 + r] = qrow[d];
        }
    }
    if (tid < 128) {
        int s = s0 + tid;
        bool ok = s < SS;
        msm[tid]  = ok ? m[bn * SS + s] : 0.f;
        esm[tid]  = ok ? e[bn * SS + s] : 0.f;
        rsum[tid] = 0.f;
    }

    int smax = min(s0 + 127, SS - 1);

    int ry8 = (tid >> 4) << 3;   // score/output row base
    int cx4 = (tid & 15) << 2;   // score col base
    int co8 = (tid & 15) << 3;   // output col base
    const float scale = 0.08838834764831845f;  // 1/sqrt(128)

    float oacc[8][8];
#pragma unroll
    for (int i = 0; i < 8; i++)
#pragma unroll
        for (int j = 0; j < 8; j++) oacc[i][j] = 0.f;

    for (int t0 = 0; t0 <= smax; t0 += 64) {
        __syncthreads();   // previous tile fully consumed (also covers init)

        // ---- load K tile transposed ----
#pragma unroll 2
        for (int j = 0; j < 8; j++) {
            int c = grp + 8 * j;
            int t = t0 + c;
            bool ok = t < SS;
            const float* krow = k + qbase + (size_t)(ok ? t : 0) * 512;
#pragma unroll
            for (int kk = 0; kk < 4; kk++) {
                int d = lane + 32 * kk;
                Ks[d * 68 + c] = ok ? krow[d] : 0.f;
            }
        }
        // ---- load V tile (float4, no transpose) ----
        for (int i = tid; i < 64 * 32; i += 256) {
            int tl = i >> 5, d4 = (i & 31) << 2;
            int t = t0 + tl;
            float4 vv = make_float4(0.f, 0.f, 0.f, 0.f);
            if (t < SS) vv = *(const float4*)(v + qbase + (size_t)t * 512 + d4);
            *(float4*)&Vs[tl * 128 + d4] = vv;
        }
        if (tid < 64) {
            int t = t0 + tid;
            asmm[tid] = (t < SS) ? a[bn * SS + t] : -1e30f;
        }
        __syncthreads();

        // ---- scores: 8 rows x 4 cols per thread over d=0..127 ----
        float sacc[8][4];
#pragma unroll
        for (int i = 0; i < 8; i++)
#pragma unroll
            for (int j = 0; j < 4; j++) sacc[i][j] = 0.f;
#pragma unroll 2
        for (int d = 0; d < 128; d++) {
            float4 qa = *(const float4*)&Qs[d * 132 + ry8];
            float4 qb = *(const float4*)&Qs[d * 132 + ry8 + 4];
            float4 k4 = *(const float4*)&Ks[d * 68 + cx4];
            float qr[8] = {qa.x, qa.y, qa.z, qa.w, qb.x, qb.y, qb.z, qb.w};
            float kr[4] = {k4.x, k4.y, k4.z, k4.w};
#pragma unroll
            for (int i = 0; i < 8; i++)
#pragma unroll
                for (int j = 0; j < 4; j++)
                    sacc[i][j] = fmaf(qr[i], kr[j], sacc[i][j]);
        }
        // weights -> Ws[r][t]
#pragma unroll
        for (int j = 0; j < 4; j++) {
            int t = t0 + cx4 + j;
            float av = asmm[cx4 + j];
#pragma unroll
            for (int i = 0; i < 8; i++) {
                int s = s0 + ry8 + i;
                float w = 0.f;
                if (t <= s && s < SS)
                    w = sacc[i][j] * scale * __expf(av - msm[ry8 + i]);
                Ws[(ry8 + i) * 68 + cx4 + j] = w;
            }
        }
        __syncthreads();

        // ---- row sums (accumulated across tiles) ----
        {
            int r = tid & 127, half = tid >> 7;
            const float* wr = &Ws[r * 68 + half * 32];
            float p = 0.f;
#pragma unroll
            for (int t = 0; t < 32; t++) p += wr[t];
            atomicAdd(&rsum[r], p);
        }

        // ---- O += W @ V : 8 rows x 8 cols per thread over t=0..63 ----
#pragma unroll 2
        for (int t = 0; t < 64; t++) {
            float4 v0 = *(const float4*)&Vs[t * 128 + co8];
            float4 v1 = *(const float4*)&Vs[t * 128 + co8 + 4];
            float vr[8] = {v0.x, v0.y, v0.z, v0.w, v1.x, v1.y, v1.z, v1.w};
#pragma unroll
            for (int i = 0; i < 8; i++) {
                float w = Ws[(ry8 + i) * 68 + t];
#pragma unroll
                for (int j = 0; j < 8; j++)
                    oacc[i][j] = fmaf(w, vr[j], oacc[i][j]);
            }
        }
    }
    __syncthreads();

    // ---- normalize + store ----
#pragma unroll
    for (int i = 0; i < 8; i++) {
        int s = s0 + ry8 + i;
        if (s >= SS) continue;
        float nr = fmaxf(fabsf(rsum[ry8 + i]), esm[ry8 + i]) + 1e-6f;
        float inv = 1.f / nr;
        float* op = out + qbase + (size_t)s * 512 + co8;
        float4 r0, r1;
        r0.x = oacc[i][0] * inv; r0.y = oacc[i][1] * inv;
        r0.z = oacc[i][2] * inv; r0.w = oacc[i][3] * inv;
        r1.x = oacc[i][4] * inv; r1.y = oacc[i][5] * inv;
        r1.z = oacc[i][6] * inv; r1.w = oacc[i][7] * inv;
        *(float4*)op = r0;
        *(float4*)(op + 4) = r1;
    }
}

// ---------------- per-head LN(128) + skip + z-gate ---------------------------
__global__ void hstate_kernel(const float* __restrict__ attn, const float* __restrict__ xca,
                              const float* __restrict__ xi, const float* __restrict__ onw,
                              const float* __restrict__ skip, float* __restrict__ out)
{
    __shared__ float red[8];
    int tok = blockIdx.x, n = blockIdx.y, c = threadIdx.x;  // 128 threads
    size_t i512 = (size_t)tok * 512 + n * 128 + c;
    float v = attn[i512];
    float s = warp_sum(v), sq = warp_sum(v * v);
    if ((c & 31) == 0) { red[c >> 5] = s; red[4 + (c >> 5)] = sq; }
    __syncthreads();
    float ts = red[0] + red[1] + red[2] + red[3];
    float tq = red[4] + red[5] + red[6] + red[7];
    float mu = ts * (1.f / 128.f);
    float var = tq * (1.f / 128.f) - mu * mu;
    float inv = rsqrtf(var + 1e-5f);
    int wc = n * 128 + c;
    float hn = (v - mu) * inv * onw[wc];
    float z = xi[(size_t)tok * 1024 + 512 + wc];
    out[i512] = (hn + skip[wc] * xca[i512]) * (z * sigmoidf_(z));
}

// ---------------- sLSTM Wx gates (16 tiny GEMMs) -----------------------------
__global__ void slstm_wx_kernel(const float* __restrict__ xc, const float* __restrict__ xn,
                                const float* __restrict__ gate_w, float* __restrict__ wx)
{
    __shared__ float wsm[64 * 65];
    __shared__ float xsm[32 * 64];
    int gh = blockIdx.x;            // g*4+h
    int g = gh >> 2, h = gh & 3;
    const float* in = (g < 2) ? xc : xn;
    const float* wg = gate_w + (size_t)gh * 4096;   // [o][d]
    int tid = threadIdx.x;
    for (int i = tid; i < 4096; i += 256) { int o = i >> 6, d = i & 63; wsm[o * 65 + d] = wg[i]; }
    int tok0 = blockIdx.y * 32;
    for (int i = tid; i < 2048; i += 256) {
        int tl = i >> 6, d = i & 63;
        xsm[i] = in[(size_t)(tok0 + tl) * 256 + h * 64 + d];
    }
    __syncthreads();
    int tl = tid >> 3;
    int obase = (tid & 7) << 3;
    const float* xr = &xsm[tl * 64];
    float acc[8] = {0, 0, 0, 0, 0, 0, 0, 0};
    for (int d = 0; d < 64; d++) {
        float xv = xr[d];
#pragma unroll
        for (int j = 0; j < 8; j++) acc[j] = fmaf(xv, wsm[(obase + j) * 65 + d], acc[j]);
    }
    size_t base = (size_t)(tok0 + tl) * 1024 + gh * 64 + obase;
#pragma unroll
    for (int j = 0; j < 8; j++) wx[base + j] = acc[j];
}

// ---------------- sLSTM recurrent scan (one CTA per (b,head)) ----------------
#define SCAN_SMEM ((4*64*65 + 64 + 256) * 4)
__global__ void slstm_scan_kernel(const float* __restrict__ wx, const float* __restrict__ recw,
                                  const float* __restrict__ bias, float* __restrict__ y)
{
    extern __shared__ float sm[];
    float* rec  = sm;                 // 4*64*65
    float* hsm  = rec + 4 * 64 * 65;  // 64
    float* raws = hsm + 64;           // 256
    int bh = blockIdx.x;
    int b = bh >> 2, h = bh & 3;
    int tid = threadIdx.x;
    int g = tid >> 6, o = tid & 63;
    for (int i = tid; i < 4 * 64 * 64; i += 256) {
        int gg = i >> 12, oo = (i >> 6) & 63, dd = i & 63;
        rec[(gg * 64 + oo) * 65 + dd] = recw[(size_t)((gg * 4 + h) * 64 + oo) * 64 + dd];
    }
    float bval = bias[(g * 4 + h) * 64 + o];
    if (tid < 64) hsm[tid] = 0.f;
    float c = 0.f, nn = 0.f, mm = 0.f;
    __syncthreads();
    const float* rrow = &rec[(g * 64 + o) * 65];
    for (int s = 0; s < SS; s++) {
        float raw = wx[((size_t)(b * SS + s)) * 1024 + (g * 4 + h) * 64 + o] + bval;
#pragma unroll 8
        for (int d = 0; d < 64; d++) raw = fmaf(hsm[d], rrow[d], raw);
        raws[tid] = raw;
        __syncthreads();
        if (tid < 64) {
            float i_ = raws[o], f_ = raws[64 + o], z_ = raws[128 + o], o_ = raws[192 + o];
            float lfm = mm + log_sigmoid(f_);
            float mn = fmaxf(i_, lfm);
            float ign = expf(i_ - mn), fgn = expf(lfm - mn);
            c  = fgn * c  + ign * tanhf(z_);
            nn = fgn * nn + ign;
            mm = mn;
            float hv = sigmoidf_(o_) * (c / nn);
            hsm[o] = hv;
            y[((size_t)(b * SS + s)) * 256 + h * 64 + o] = hv;
        }
        __syncthreads();
    }
}

// ---------------- sLSTM group norm (per-head LN over 64) + residual ----------
__global__ void slstm_gn_kernel(const float* __restrict__ y, const float* __restrict__ w,
                                float* __restrict__ h_io)
{
    int tok = blockIdx.x;
    int h = threadIdx.x >> 5, lane = threadIdx.x & 31;
    size_t base = (size_t)tok * 256 + h * 64;
    float v0 = y[base + lane], v1 = y[base + 32 + lane];
    float s = warp_sum(v0 + v1);
    float sq = warp_sum(v0 * v0 + v1 * v1);
    float mu = s * (1.f / 64.f);
    float var = sq * (1.f / 64.f) - mu * mu;
    float inv = rsqrtf(var + 1e-5f);
    h_io[base + lane]      += (v0 - mu) * inv * w[h * 64 + lane];
    h_io[base + 32 + lane] += (v1 - mu) * inv * w[h * 64 + 32 + lane];
}

// ---------------- gated FFN activation ---------------------------------------
__global__ void gelu_gate_kernel(const float* __restrict__ mid, float* __restrict__ act)
{
    int idx = blockIdx.x * blockDim.x + threadIdx.x;
    if (idx >= BS_TOK * 384) return;
    int tok = idx / 384, j = idx % 384;
    float gt = mid[(size_t)tok * 768 + j];
    float up = mid[(size_t)tok * 768 + 384 + j];
    float t = tanhf(0.7978845608028654f * (gt + 0.044715f * gt * gt * gt));
    act[(size_t)tok * 384 + j] = 0.5f * gt * (1.f + t) * up;
}

// ---------------- mean pool over S -------------------------------------------
__global__ void pool_kernel(const float* __restrict__ xn, float* __restrict__ pooled)
{
    int b = blockIdx.x, c = threadIdx.x;
    float acc = 0.f;
    for (int s = 0; s < SS; s++) acc += xn[((size_t)(b * SS + s)) * 256 + c];
    pooled[b * 256 + c] = acc * (1.f / 199.f);
}

// ---------------- classification heads ---------------------------------------
__global__ void heads_kernel(const float* __restrict__ pooled,
                             const float* __restrict__ we, const float* __restrict__ be,
                             const float* __restrict__ ws, const float* __restrict__ bs_,
                             float* __restrict__ out)
{
    __shared__ float p[256];
    int b = blockIdx.x, tid = threadIdx.x;
    p[tid] = pooled[b * 256 + tid];
    __syncthreads();
    if (tid < 7) {
        float a = be[tid];
        for (int i = 0; i < 256; i++) a = fmaf(p[i], we[i * 7 + tid], a);
        out[b * 7 + tid] = a;
    } else if (tid < 10) {
        int j = tid - 7;
        float a = bs_[j];
        for (int i = 0; i < 256; i++) a = fmaf(p[i], ws[i * 3 + j], a);
        out[BB * 7 + b * 3 + j] = a;
    }
}

// ---------------- host orchestration -----------------------------------------
extern "C" void kernel_launch(void* const* d_in, const int* in_sizes, int n_in,
                              void* d_out, int out_size)
{
    (void)in_sizes; (void)n_in; (void)out_size;
    const float* x          = (const float*)d_in[0];
    const float* w_down     = (const float*)d_in[1];
    const float* b_down     = (const float*)d_in[2];
    const float* m_ln_w     = (const float*)d_in[3];
    const float* m_proj_up  = (const float*)d_in[4];
    const float* m_conv_w   = (const float*)d_in[5];
    const float* m_conv_b   = (const float*)d_in[6];
    const float* m_q_w      = (const float*)d_in[7];
    const float* m_k_w      = (const float*)d_in[8];
    const float* m_v_w      = (const float*)d_in[9];
    const float* m_ig_w     = (const float*)d_in[10];
    const float* m_ig_b     = (const float*)d_in[11];
    const float* m_fg_w     = (const float*)d_in[12];
    const float* m_fg_b     = (const float*)d_in[13];
    const float* m_skip     = (const float*)d_in[14];
    const float* m_outnorm  = (const float*)d_in[15];
    const float* m_proj_dn  = (const float*)d_in[16];
    const float* s_ln_w     = (const float*)d_in[17];
    const float* s_conv_w   = (const float*)d_in[18];
    const float* s_conv_b   = (const float*)d_in[19];
    const float* s_gate_w   = (const float*)d_in[20];
    const float* s_rec_w    = (const float*)d_in[21];
    const float* s_bias     = (const float*)d_in[22];
    const float* s_gn_w     = (const float*)d_in[23];
    const float* s_ln2_w    = (const float*)d_in[24];
    const float* s_ffn_up   = (const float*)d_in[25];
    const float* s_ffn_dn   = (const float*)d_in[26];
    const float* post_ln_w  = (const float*)d_in[27];
    const float* w_emo      = (const float*)d_in[28];
    const float* b_emo      = (const float*)d_in[29];
    const float* w_sen      = (const float*)d_in[30];
    const float* b_sen      = (const float*)d_in[31];

    float *h_, *xn_, *big_, *xca_, *q_, *k_, *v_, *hs_;
    float *ig_, *fg_, *a_, *mm_, *e_, *pool_;
    cudaGetSymbolAddress((void**)&h_,   g_h);
    cudaGetSymbolAddress((void**)&xn_,  g_xn);
    cudaGetSymbolAddress((void**)&big_, g_big);
    cudaGetSymbolAddress((void**)&xca_, g_xca);
    cudaGetSymbolAddress((void**)&q_,   g_q);
    cudaGetSymbolAddress((void**)&k_,   g_k);
    cudaGetSymbolAddress((void**)&v_,   g_v);
    cudaGetSymbolAddress((void**)&hs_,  g_hs);
    cudaGetSymbolAddress((void**)&ig_,  g_ig);
    cudaGetSymbolAddress((void**)&fg_,  g_fg);
    cudaGetSymbolAddress((void**)&a_,   g_a);
    cudaGetSymbolAddress((void**)&mm_,  g_m);
    cudaGetSymbolAddress((void**)&e_,   g_e);
    cudaGetSymbolAddress((void**)&pool_, g_pool);

    cudaFuncSetAttribute(attn2_kernel, cudaFuncAttributeMaxDynamicSharedMemorySize, ATTN2_SMEM);
    cudaFuncSetAttribute(slstm_scan_kernel, cudaFuncAttributeMaxDynamicSharedMemorySize, SCAN_SMEM);

    const int LN_GRID = BS_TOK / 8;  // 1592
    const int MG = (BS_TOK + 127) / 128;   // 100 row tiles for GEMM

    // h = x @ w_down + b_down
    gemm_kernel<<<dim3(2, MG), 256>>>(x, w_down, h_, BS_TOK, 256, 1024, b_down, 0);

    int mi = 0, si = 0;
    for (int blk = 0; blk < 7; blk++) {
        if (blk == 1 || blk == 4) {
            // ---- sLSTM block ----
            ln_kernel<<<LN_GRID, 256>>>(h_, s_ln_w + si * 256, xn_, BS_TOK, 0);
            conv_silu_kernel<<<(BS_TOK * 256 + 255) / 256, 256>>>(
                xn_, s_conv_w + si * 1024, s_conv_b + si * 256, xca_, 256, 256);
            slstm_wx_kernel<<<dim3(16, BS_TOK / 32), 256>>>(
                xca_, xn_, s_gate_w + (size_t)si * 65536, big_);
            slstm_scan_kernel<<<256, 256, SCAN_SMEM>>>(
                big_, s_rec_w + (size_t)si * 65536, s_bias + si * 1024, hs_);
            slstm_gn_kernel<<<BS_TOK, 128>>>(hs_, s_gn_w + si * 256, h_);
            // FFN
            ln_kernel<<<LN_GRID, 256>>>(h_, s_ln2_w + si * 256, xn_, BS_TOK, 0);
            gemm_kernel<<<dim3(6, MG), 256>>>(xn_, s_ffn_up + (size_t)si * 196608, big_,
                                              BS_TOK, 768, 256, nullptr, 0);
            gelu_gate_kernel<<<(BS_TOK * 384 + 255) / 256, 256>>>(big_, hs_);
            gemm_kernel<<<dim3(2, MG), 256>>>(hs_, s_ffn_dn + (size_t)si * 98304, h_,
                                              BS_TOK, 256, 384, nullptr, 1);
            si++;
        } else {
            // ---- mLSTM block ----
            ln_kernel<<<LN_GRID, 256>>>(h_, m_ln_w + mi * 256, xn_, BS_TOK, 0);
            gemm_kernel<<<dim3(8, MG), 256>>>(xn_, m_proj_up + (size_t)mi * 262144, big_,
                                              BS_TOK, 1024, 256, nullptr, 0);
            conv_silu_kernel<<<(BS_TOK * 512 + 255) / 256, 256>>>(
                big_, m_conv_w + mi * 2048, m_conv_b + mi * 512, xca_, 512, 1024);
            headwise_kernel<<<BS_TOK * 128 / 256, 256>>>(xca_, 512, m_q_w + mi * 2048, q_);
            headwise_kernel<<<BS_TOK * 128 / 256, 256>>>(xca_, 512, m_k_w + mi * 2048, k_);
            headwise_kernel<<<BS_TOK * 128 / 256, 256>>>(big_, 1024, m_v_w + mi * 2048, v_);
            mgates_kernel<<<BS_TOK / 8, 256>>>(q_, k_, v_,
                m_ig_w + mi * 6144, m_ig_b + mi * 4,
                m_fg_w + mi * 6144, m_fg_b + mi * 4, ig_, fg_);
            gateprep_kernel<<<256, 32>>>(ig_, fg_, a_, mm_, e_);
            attn2_kernel<<<dim3(256, 2), 256, ATTN2_SMEM>>>(q_, k_, v_, a_, mm_, e_, q_);
            hstate_kernel<<<dim3(BS_TOK, 4), 128>>>(q_, xca_, big_,
                m_outnorm + mi * 512, m_skip + mi * 512, hs_);
            gemm_kernel<<<dim3(2, MG), 256>>>(hs_, m_proj_dn + (size_t)mi * 131072, h_,
                                              BS_TOK, 256, 512, nullptr, 1);
            mi++;
        }
    }

    // post LN + SELU, mean pool, heads
    ln_kernel<<<LN_GRID, 256>>>(h_, post_ln_w, xn_, BS_TOK, 1);
    pool_kernel<<<BB, 256>>>(xn_, pool_);
    heads_kernel<<<BB, 256>>>(pool_, w_emo, b_emo, w_sen, b_sen, (float*)d_out);
}